// round 1
// baseline (speedup 1.0000x reference)
#include <cuda_runtime.h>

// ============================================================
// Compile-time Clebsch-Gordan (exact transcription of the
// reference Racah formula, evaluated by the C++ frontend so
// every coefficient becomes an FFMA immediate in SASS).
// ============================================================
__host__ __device__ constexpr double cfact(int n) {
    double r = 1.0;
    for (int i = 2; i <= n; ++i) r *= (double)i;
    return r;
}
__host__ __device__ constexpr double csqrt_(double x) {
    double g = x > 1.0 ? x : 1.0;
    for (int i = 0; i < 100; ++i) g = 0.5 * (g + x / g);
    return g;
}
__host__ __device__ constexpr double cgc(int j1, int m1, int j2, int m2, int j, int m) {
    // caller guarantees m1+m2==m and |m2|<=j2
    double pre = csqrt_((2.0 * j + 1.0) * cfact(j + j1 - j2) * cfact(j - j1 + j2) *
                        cfact(j1 + j2 - j) / cfact(j1 + j2 + j + 1));
    pre = pre * csqrt_(cfact(j + m) * cfact(j - m) * cfact(j1 - m1) * cfact(j1 + m1) *
                       cfact(j2 - m2) * cfact(j2 + m2));
    int vmin = 0;
    if (j2 - j - m1 > vmin) vmin = j2 - j - m1;
    if (j1 + m2 - j > vmin) vmin = j1 + m2 - j;
    int vmax = j1 + j2 - j;
    if (j1 - m1 < vmax) vmax = j1 - m1;
    if (j2 + m2 < vmax) vmax = j2 + m2;
    double s = 0.0;
    for (int v = vmin; v <= vmax; ++v) {
        double t = 1.0 / (cfact(v) * cfact(j1 + j2 - j - v) * cfact(j1 - m1 - v) *
                          cfact(j2 + m2 - v) * cfact(j - j2 + m1 + v) * cfact(j - j1 - m2 + v));
        s += (v % 2 == 0) ? t : -t;
    }
    return pre * s;
}

// ============================================================
// Fully unrolled CG contraction with immediate coefficients.
// float4 = 2 complex channels: (re0, im0, re1, im1).
// ============================================================
template <int L1, int L2, int L, int MI, int M1I>
__device__ __forceinline__ void cg_term(float4& acc, const float4 (&p)[2 * L1 + 1][2 * L2 + 1]) {
    constexpr int m  = MI - L;
    constexpr int m1 = M1I - L1;
    constexpr int m2 = m - m1;
    if constexpr (m2 >= -L2 && m2 <= L2) {
        constexpr float c = (float)cgc(L1, m1, L2, m2, L, m);
        if constexpr (c != 0.0f) {
            const float4 q = p[M1I][m2 + L2];
            acc.x = fmaf(c, q.x, acc.x);
            acc.y = fmaf(c, q.y, acc.y);
            acc.z = fmaf(c, q.z, acc.z);
            acc.w = fmaf(c, q.w, acc.w);
        }
    }
}

template <int L1, int L2, int L, int MI, int M1I>
__device__ __forceinline__ void cg_terms(float4& acc, const float4 (&p)[2 * L1 + 1][2 * L2 + 1]) {
    cg_term<L1, L2, L, MI, M1I>(acc, p);
    if constexpr (M1I + 1 <= 2 * L1) cg_terms<L1, L2, L, MI, M1I + 1>(acc, p);
}

template <int L1, int L2, int L, int MI>
__device__ __forceinline__ void cg_rows(float4 (&o)[2 * L + 1], const float4 (&p)[2 * L1 + 1][2 * L2 + 1]) {
    float4 acc = make_float4(0.f, 0.f, 0.f, 0.f);
    cg_terms<L1, L2, L, MI, 0>(acc, p);
    o[MI] = acc;
    if constexpr (MI + 1 <= 2 * L) cg_rows<L1, L2, L, MI + 1>(o, p);
}

__device__ __forceinline__ float4 cmul(const float4 a, const float4 b) {
    return make_float4(a.x * b.x - a.y * b.y, a.x * b.y + a.y * b.x,
                       a.z * b.z - a.w * b.w, a.z * b.w + a.w * b.z);
}
__device__ __forceinline__ float4 neg4(const float4 v) {
    return make_float4(-v.x, -v.y, -v.z, -v.w);
}

// ============================================================
// Output layout (float4 units).
// Parts l=0..4 concatenated: shapes (1024, 2l+1, n_l*512, 2):
//   n = {3, 6, 6, 3, 1}
// ============================================================
static constexpr int P1 = 786432;    // 3145728  / 4
static constexpr int P2 = 5505024;   // 22020096 / 4
static constexpr int P3 = 13369344;  // 53477376 / 4
static constexpr int P4 = 18874368;  // 75497472 / 4

__global__ void __launch_bounds__(256) cg_kernel(
    const float4* __restrict__ x0, const float4* __restrict__ x1,
    const float4* __restrict__ x2, float4* __restrict__ out) {
    const int c4 = threadIdx.x;  // 0..255  (channel pair index)
    const int b  = blockIdx.x;   // 0..1023 (batch)

    const float4 a0 = x0[b * 256 + c4];
    float4 a1[3], a2[5];
#pragma unroll
    for (int i = 0; i < 3; ++i) a1[i] = x1[(b * 3 + i) * 256 + c4];
#pragma unroll
    for (int i = 0; i < 5; ++i) a2[i] = x2[(b * 5 + i) * 256 + c4];

    const float4 zf = make_float4(0.f, 0.f, 0.f, 0.f);

    // ---- (0,0,0): l=0, k=0
    out[b * 768 + c4] = cmul(a0, a0);

    // ---- (0,1,1) & (1,0,1): identical (C=1). Also l=1 zero blocks
    //      (1,1,1) k=2 and (2,2,1) k=5 (antisymmetric self-products).
#pragma unroll
    for (int q = 0; q < 3; ++q) {
        const float4 p   = cmul(a0, a1[q]);
        const int   base = P1 + (b * 3 + q) * 1536 + c4;
        out[base          ] = p;   // k=0 (0,1)
        out[base + 1 * 256] = p;   // k=1 (1,0)
        out[base + 2 * 256] = zf;  // k=2 (1,1,1) == 0
        out[base + 5 * 256] = zf;  // k=5 (2,2,1) == 0
    }

    // ---- (0,2,2) & (2,0,2): identical (C=1)
#pragma unroll
    for (int q = 0; q < 5; ++q) {
        const float4 p   = cmul(a0, a2[q]);
        const int   base = P2 + (b * 5 + q) * 1536 + c4;
        out[base          ] = p;  // k=0 (0,2)
        out[base + 3 * 256] = p;  // k=3 (2,0)
    }

    // ---- (1,1) group: l=0 (k=1), l=2 (k=1)
    {
        float4 p11[3][3];
#pragma unroll
        for (int i = 0; i < 3; ++i)
#pragma unroll
            for (int j = i; j < 3; ++j) {
                p11[i][j] = cmul(a1[i], a1[j]);
                if (j != i) p11[j][i] = p11[i][j];
            }
        float4 o0[1];
        cg_rows<1, 1, 0, 0>(o0, p11);
        out[b * 768 + 256 + c4] = o0[0];  // l=0, k=1
        float4 o2[5];
        cg_rows<1, 1, 2, 0>(o2, p11);
#pragma unroll
        for (int mi = 0; mi < 5; ++mi)
            out[P2 + (b * 5 + mi) * 1536 + 1 * 256 + c4] = o2[mi];  // l=2, k=1
    }

    // ---- (1,2)/(2,1) group: (2,1,l) = (-1)^(3-l) * (1,2,l)
    {
        float4 p12[3][5];
#pragma unroll
        for (int i = 0; i < 3; ++i)
#pragma unroll
            for (int j = 0; j < 5; ++j) p12[i][j] = cmul(a1[i], a2[j]);

        float4 r1[3];
        cg_rows<1, 2, 1, 0>(r1, p12);
#pragma unroll
        for (int mi = 0; mi < 3; ++mi) {
            const int base = P1 + (b * 3 + mi) * 1536 + c4;
            out[base + 3 * 256] = r1[mi];  // k=3 (1,2,1)
            out[base + 4 * 256] = r1[mi];  // k=4 (2,1,1), sign +1
        }
        float4 r2[5];
        cg_rows<1, 2, 2, 0>(r2, p12);
#pragma unroll
        for (int mi = 0; mi < 5; ++mi) {
            const int base = P2 + (b * 5 + mi) * 1536 + c4;
            out[base + 2 * 256] = r2[mi];        // k=2 (1,2,2)
            out[base + 4 * 256] = neg4(r2[mi]);  // k=4 (2,1,2), sign -1
        }
        float4 r3[7];
        cg_rows<1, 2, 3, 0>(r3, p12);
#pragma unroll
        for (int mi = 0; mi < 7; ++mi) {
            const int base = P3 + (b * 7 + mi) * 768 + c4;
            out[base          ] = r3[mi];  // k=0 (1,2,3)
            out[base + 1 * 256] = r3[mi];  // k=1 (2,1,3), sign +1
            out[base + 2 * 256] = zf;      // k=2 (2,2,3) == 0
        }
    }

    // ---- (2,2) group: l=0 (k=2), l=2 (k=5), l=4 (k=0)
    {
        float4 p22[5][5];
#pragma unroll
        for (int i = 0; i < 5; ++i)
#pragma unroll
            for (int j = i; j < 5; ++j) {
                p22[i][j] = cmul(a2[i], a2[j]);
                if (j != i) p22[j][i] = p22[i][j];
            }
        float4 o0[1];
        cg_rows<2, 2, 0, 0>(o0, p22);
        out[b * 768 + 2 * 256 + c4] = o0[0];  // l=0, k=2
        float4 o2[5];
        cg_rows<2, 2, 2, 0>(o2, p22);
#pragma unroll
        for (int mi = 0; mi < 5; ++mi)
            out[P2 + (b * 5 + mi) * 1536 + 5 * 256 + c4] = o2[mi];  // l=2, k=5
        float4 o4[9];
        cg_rows<2, 2, 4, 0>(o4, p22);
#pragma unroll
        for (int mi = 0; mi < 9; ++mi)
            out[P4 + (b * 9 + mi) * 256 + c4] = o4[mi];  // l=4, k=0
    }
}

extern "C" void kernel_launch(void* const* d_in, const int* in_sizes, int n_in,
                              void* d_out, int out_size) {
    // Identify inputs by element count (robust to metadata ordering).
    const float4* x0 = nullptr;
    const float4* x1 = nullptr;
    const float4* x2 = nullptr;
    for (int i = 0; i < n_in; ++i) {
        if (in_sizes[i] == 1024 * 1 * 512 * 2)      x0 = (const float4*)d_in[i];
        else if (in_sizes[i] == 1024 * 3 * 512 * 2) x1 = (const float4*)d_in[i];
        else if (in_sizes[i] == 1024 * 5 * 512 * 2) x2 = (const float4*)d_in[i];
    }
    cg_kernel<<<1024, 256>>>(x0, x1, x2, (float4*)d_out);
}